// round 15
// baseline (speedup 1.0000x reference)
#include <cuda_runtime.h>
#include <math_constants.h>

#define H 1024
#define S 32768
#define GRID 740                 // 148 SMs x 5 CTAs, all resident
#define BLK 256
#define NSLICES 256              // P0: 4 d-rows per slice
#define MAX_ROWS 48              // max rows per block (ceil(S/GRID)=45)

// Scratch (no allocations allowed)
__device__ float g_vpart[NSLICES * H];    // 1 MB
__device__ float g_v[H];
__device__ float g_bmax[GRID];
__device__ float g_bsum[GRID];
__device__ unsigned g_bar;   // zero-init; self-resetting
__device__ unsigned g_done;

__device__ __forceinline__ void grid_sync(unsigned target) {
    __syncthreads();
    __threadfence();
    if (threadIdx.x == 0) {
        atomicAdd(&g_bar, 1u);
        while (*(volatile unsigned*)&g_bar < target) __nanosleep(64);
    }
    __syncthreads();
}

__global__ __launch_bounds__(BLK, 5) void fused_kernel(
    const float* __restrict__ W,
    const float* __restrict__ hidden,
    const float* __restrict__ enc,
    float* __restrict__ out)
{
    __shared__ float sv[H];              // v staged once (4 KB)
    __shared__ float s_sc[MAX_ROWS];
    __shared__ float red[BLK];

    const int tid  = threadIdx.x;
    const int warp = tid >> 5;
    const int lane = tid & 31;
    const int b    = blockIdx.x;

    // ---------------- P0: v partials — blocks 0..255, 4 d-rows each --------
    // 16 fully-unrolled independent W loads per thread -> 4 MB in flight.
    if (b < NSLICES) {
        const int d0 = b * 4;
        float acc0 = 0.f, acc1 = 0.f, acc2 = 0.f, acc3 = 0.f;
#pragma unroll
        for (int dd = 0; dd < 4; dd++) {
            const float hd = hidden[d0 + dd];
            const float* wr = W + (size_t)(d0 + dd) * H;
            acc0 += wr[tid      ] * hd;
            acc1 += wr[tid + 256] * hd;
            acc2 += wr[tid + 512] * hd;
            acc3 += wr[tid + 768] * hd;
        }
        g_vpart[b * H + tid      ] = acc0;
        g_vpart[b * H + tid + 256] = acc1;
        g_vpart[b * H + tid + 512] = acc2;
        g_vpart[b * H + tid + 768] = acc3;
    }
    grid_sync(GRID);

    // ---------------- P1: reduce 256 partials -> g_v (blocks 0..127) -------
    if (b < 128) {
        const int h = b * 8 + warp;
        float a0 = g_vpart[(lane      ) * H + h];
        float a1 = g_vpart[(lane +  32) * H + h];
        float a2 = g_vpart[(lane +  64) * H + h];
        float a3 = g_vpart[(lane +  96) * H + h];
        float a4 = g_vpart[(lane + 128) * H + h];
        float a5 = g_vpart[(lane + 160) * H + h];
        float a6 = g_vpart[(lane + 192) * H + h];
        float a7 = g_vpart[(lane + 224) * H + h];
        float a = ((a0 + a1) + (a2 + a3)) + ((a4 + a5) + (a6 + a7));
#pragma unroll
        for (int o = 16; o > 0; o >>= 1) a += __shfl_xor_sync(0xFFFFFFFFu, a, o);
        if (lane == 0) g_v[h] = a;
    }
    grid_sync(2 * GRID);

    // ---------------- P2: free-running LDG stream (no per-tile syncs) ------
    reinterpret_cast<float4*>(sv)[tid] = reinterpret_cast<const float4*>(g_v)[tid];
    __syncthreads();

    const int r0    = (int)(((long long)b * S) / GRID);
    const int r1    = (int)(((long long)(b + 1) * S) / GRID);
    const int nrows = r1 - r0;                         // 44 or 45

    const float4* v4 = reinterpret_cast<const float4*>(sv);

#pragma unroll 1
    for (int rr = warp; rr < nrows; rr += 8) {
        const size_t row = (size_t)(r0 + rr);
        const float4* r = reinterpret_cast<const float4*>(enc + row * H);
        float acc = 0.f;
#pragma unroll
        for (int k = 0; k < 8; k++) {
            float4 e  = r[lane + k * 32];
            float4 vv = v4[lane + k * 32];
            acc += e.x * vv.x + e.y * vv.y + e.z * vv.z + e.w * vv.w;
        }
#pragma unroll
        for (int o = 16; o > 0; o >>= 1) acc += __shfl_xor_sync(0xFFFFFFFFu, acc, o);
        if (lane == 0) s_sc[rr] = acc;
    }
    __syncthreads();

    // block (max, expsum) over its nrows scores
    red[tid] = (tid < nrows) ? s_sc[tid] : -CUDART_INF_F;
    __syncthreads();
#pragma unroll
    for (int s = 128; s > 0; s >>= 1) {
        if (tid < s) red[tid] = fmaxf(red[tid], red[tid + s]);
        __syncthreads();
    }
    const float Mb = red[0];
    __syncthreads();
    red[tid] = (tid < nrows) ? __expf(s_sc[tid] - Mb) : 0.f;
    __syncthreads();
#pragma unroll
    for (int s = 128; s > 0; s >>= 1) {
        if (tid < s) red[tid] += red[tid + s];
        __syncthreads();
    }
    if (tid == 0) {
        g_bmax[b] = Mb;
        g_bsum[b] = red[0];
    }
    grid_sync(3 * GRID);

    // ---------------- P3: redundant pair-reduce (740 pairs) + normalize ----
    float pm0 = g_bmax[tid];
    float ps0 = g_bsum[tid];
    float pm1 = g_bmax[tid + 256];
    float ps1 = g_bsum[tid + 256];
    float pm2 = -CUDART_INF_F, ps2 = 0.f;
    if (tid < GRID - 512) {                            // tid < 228
        pm2 = g_bmax[tid + 512];
        ps2 = g_bsum[tid + 512];
    }
    red[tid] = fmaxf(fmaxf(pm0, pm1), pm2);
    __syncthreads();
#pragma unroll
    for (int s = 128; s > 0; s >>= 1) {
        if (tid < s) red[tid] = fmaxf(red[tid], red[tid + s]);
        __syncthreads();
    }
    const float M = red[0];
    __syncthreads();
    red[tid] = ps0 * __expf(pm0 - M) + ps1 * __expf(pm1 - M) + ps2 * __expf(pm2 - M);
    __syncthreads();
#pragma unroll
    for (int s = 128; s > 0; s >>= 1) {
        if (tid < s) red[tid] += red[tid + s];
        __syncthreads();
    }
    const float inv = 1.0f / red[0];

    if (tid < nrows)
        out[r0 + tid] = __expf(s_sc[tid] - M) * inv;

    // ---------------- reset counters for next graph replay ------------------
    __threadfence();
    __syncthreads();
    if (tid == 0) {
        unsigned d = atomicAdd(&g_done, 1u) + 1;
        if (d == GRID) {
            g_bar = 0;
            g_done = 0;
            __threadfence();
        }
    }
}

// ---------------------------------------------------------------------------
extern "C" void kernel_launch(void* const* d_in, const int* in_sizes, int n_in,
                              void* d_out, int out_size) {
    const float* hidden = (const float*)d_in[0];   // [H]
    const float* enc    = (const float*)d_in[1];   // [S, H]
    const float* W      = (const float*)d_in[2];   // [H, H]
    float* out          = (float*)d_out;           // [S]

    fused_kernel<<<GRID, BLK>>>(W, hidden, enc, out);
}

// round 16
// speedup vs baseline: 1.2753x; 1.2753x over previous
#include <cuda_runtime.h>
#include <math_constants.h>

#define H 1024
#define S 32768
#define GRID 592                 // 148 SMs x 4 CTAs, all resident
#define BLK 256
#define STAGES 3
#define TROWS 4                  // rows per tile
#define TILE_BYTES (TROWS * H * 4)   // 16384
#define TILE_F4 (TROWS * H / 4)      // 1024
#define SMEM_DYN (STAGES * TILE_BYTES) // 49152
#define NSLICES 256              // P0: 4 d-rows per slice
#define MAX_ROWS 56              // ceil(S/GRID) = 56

// Scratch (no allocations allowed)
__device__ float g_vpart[NSLICES * H];    // 1 MB
__device__ float g_v[H];
__device__ float g_bmax[GRID];
__device__ float g_bsum[GRID];
__device__ unsigned g_bar;   // zero-init; self-resetting
__device__ unsigned g_done;

__device__ __forceinline__ void grid_sync(unsigned target) {
    __syncthreads();
    __threadfence();
    if (threadIdx.x == 0) {
        atomicAdd(&g_bar, 1u);
        while (*(volatile unsigned*)&g_bar < target) __nanosleep(64);
    }
    __syncthreads();
}

__device__ __forceinline__ void mbar_wait(unsigned mbar, unsigned parity) {
    asm volatile(
        "{\n\t"
        ".reg .pred P;\n\t"
        "W_%=:\n\t"
        "mbarrier.try_wait.parity.acquire.cta.shared::cta.b64 P, [%0], %1, 0x989680;\n\t"
        "@P bra D_%=;\n\t"
        "bra W_%=;\n\t"
        "D_%=:\n\t"
        "}" :: "r"(mbar), "r"(parity) : "memory");
}

__device__ __forceinline__ void bulk_fetch(unsigned ba, float4* dst,
                                           const char* src, unsigned bytes) {
    asm volatile("mbarrier.arrive.expect_tx.shared.b64 _, [%0], %1;"
                 :: "r"(ba), "r"(bytes) : "memory");
    unsigned da = (unsigned)__cvta_generic_to_shared(dst);
    asm volatile("cp.async.bulk.shared::cta.global.mbarrier::complete_tx::bytes "
                 "[%0], [%1], %2, [%3];"
                 :: "r"(da), "l"(src), "r"(bytes), "r"(ba) : "memory");
}

__global__ __launch_bounds__(BLK, 4) void fused_kernel(
    const float* __restrict__ W,
    const float* __restrict__ hidden,
    const float* __restrict__ enc,
    float* __restrict__ out)
{
    extern __shared__ float4 tile[];                   // [STAGES][TILE_F4]
    __shared__ __align__(8) unsigned long long mbar[STAGES];
    __shared__ float s_sc[MAX_ROWS];
    __shared__ float red[BLK];

    const int tid  = threadIdx.x;
    const int warp = tid >> 5;
    const int lane = tid & 31;
    const int b    = blockIdx.x;

    // row range for this block (55 or 56 rows)
    const int r0    = (int)(((long long)b * S) / GRID);
    const int r1    = (int)(((long long)(b + 1) * S) / GRID);
    const int nrows = r1 - r0;
    const int ntiles = (nrows + TROWS - 1) / TROWS;    // 14

    // mbarrier init + zero the score accumulators
    if (tid == 0) {
#pragma unroll
        for (int s = 0; s < STAGES; s++) {
            unsigned a = (unsigned)__cvta_generic_to_shared(&mbar[s]);
            asm volatile("mbarrier.init.shared.b64 [%0], 1;" :: "r"(a) : "memory");
        }
        asm volatile("fence.proxy.async.shared::cta;" ::: "memory");
    }
    if (tid < MAX_ROWS) s_sc[tid] = 0.f;

    // ---------------- P0: v partials — blocks 0..255, 4 d-rows each --------
    if (b < NSLICES) {
        const int d0 = b * 4;
        float acc0 = 0.f, acc1 = 0.f, acc2 = 0.f, acc3 = 0.f;
#pragma unroll
        for (int dd = 0; dd < 4; dd++) {
            const float hd = hidden[d0 + dd];
            const float* wr = W + (size_t)(d0 + dd) * H;
            acc0 += wr[tid      ] * hd;
            acc1 += wr[tid + 256] * hd;
            acc2 += wr[tid + 512] * hd;
            acc3 += wr[tid + 768] * hd;
        }
        g_vpart[b * H + tid      ] = acc0;
        g_vpart[b * H + tid + 256] = acc1;
        g_vpart[b * H + tid + 512] = acc2;
        g_vpart[b * H + tid + 768] = acc3;
    }
    grid_sync(GRID);

    // ---------------- P1: reduce 256 partials -> g_v (blocks 0..127) -------
    if (b < 128) {
        const int h = b * 8 + warp;
        float a0 = g_vpart[(lane      ) * H + h];
        float a1 = g_vpart[(lane +  32) * H + h];
        float a2 = g_vpart[(lane +  64) * H + h];
        float a3 = g_vpart[(lane +  96) * H + h];
        float a4 = g_vpart[(lane + 128) * H + h];
        float a5 = g_vpart[(lane + 160) * H + h];
        float a6 = g_vpart[(lane + 192) * H + h];
        float a7 = g_vpart[(lane + 224) * H + h];
        float a = ((a0 + a1) + (a2 + a3)) + ((a4 + a5) + (a6 + a7));
#pragma unroll
        for (int o = 16; o > 0; o >>= 1) a += __shfl_xor_sync(0xFFFFFFFFu, a, o);
        if (lane == 0) g_v[h] = a;
    }
    grid_sync(2 * GRID);

    // ---------------- P2: TMA pipeline, 2 warps per row --------------------
    // warp w handles row (w>>1) of each 4-row tile, half (w&1) of its 1024 cols.
    const int myrow  = warp >> 1;                      // 0..3
    const int half   = warp & 1;
    float4 vr[4];
    const float4* v4 = reinterpret_cast<const float4*>(g_v);
#pragma unroll
    for (int k = 0; k < 4; k++) vr[k] = v4[half * 128 + lane + k * 32];

    const char* src_base = reinterpret_cast<const char*>(enc) + (size_t)r0 * H * 4;

    if (tid == 0) {
#pragma unroll
        for (int s = 0; s < STAGES; s++) {
            unsigned ba = (unsigned)__cvta_generic_to_shared(&mbar[s]);
            const int rows_t = min(TROWS, nrows - s * TROWS);
            bulk_fetch(ba, tile + s * TILE_F4,
                       src_base + (size_t)s * TILE_BYTES,
                       (unsigned)(rows_t * H * 4));
        }
    }

#pragma unroll 1
    for (int t = 0; t < ntiles; t++) {
        const int st = t % STAGES;
        unsigned ba = (unsigned)__cvta_generic_to_shared(&mbar[st]);
        mbar_wait(ba, (t / STAGES) & 1);

        const int rows_t = min(TROWS, nrows - t * TROWS);
        if (myrow < rows_t) {
            const float4* rowp = tile + st * TILE_F4 + myrow * (H / 4) + half * 128;
            float acc = 0.f;
#pragma unroll
            for (int k = 0; k < 4; k++) {
                float4 e = rowp[lane + k * 32];
                acc += e.x * vr[k].x + e.y * vr[k].y + e.z * vr[k].z + e.w * vr[k].w;
            }
#pragma unroll
            for (int o = 16; o > 0; o >>= 1) acc += __shfl_xor_sync(0xFFFFFFFFu, acc, o);
            // exactly two contributions per row; fp add is commutative -> deterministic
            if (lane == 0) atomicAdd(&s_sc[t * TROWS + myrow], acc);
        }

        __syncthreads();   // all warps done reading stage st
        if (tid == 0 && t + STAGES < ntiles) {
            const int rows_n = min(TROWS, nrows - (t + STAGES) * TROWS);
            bulk_fetch(ba, tile + st * TILE_F4,
                       src_base + (size_t)(t + STAGES) * TILE_BYTES,
                       (unsigned)(rows_n * H * 4));
        }
    }

    // ---------------- block (max, expsum) over its nrows scores ------------
    red[tid] = (tid < nrows) ? s_sc[tid] : -CUDART_INF_F;
    __syncthreads();
#pragma unroll
    for (int s = 128; s > 0; s >>= 1) {
        if (tid < s) red[tid] = fmaxf(red[tid], red[tid + s]);
        __syncthreads();
    }
    const float Mb = red[0];
    __syncthreads();
    red[tid] = (tid < nrows) ? __expf(s_sc[tid] - Mb) : 0.f;
    __syncthreads();
#pragma unroll
    for (int s = 128; s > 0; s >>= 1) {
        if (tid < s) red[tid] += red[tid + s];
        __syncthreads();
    }
    if (tid == 0) {
        g_bmax[b] = Mb;
        g_bsum[b] = red[0];
    }
    grid_sync(3 * GRID);

    // ---------------- P3: redundant pair-reduce (592 pairs) + normalize ----
    float pm0 = g_bmax[tid];
    float ps0 = g_bsum[tid];
    float pm1 = g_bmax[tid + 256];
    float ps1 = g_bsum[tid + 256];
    float pm2 = -CUDART_INF_F, ps2 = 0.f;
    if (tid < GRID - 512) {                            // tid < 80
        pm2 = g_bmax[tid + 512];
        ps2 = g_bsum[tid + 512];
    }
    red[tid] = fmaxf(fmaxf(pm0, pm1), pm2);
    __syncthreads();
#pragma unroll
    for (int s = 128; s > 0; s >>= 1) {
        if (tid < s) red[tid] = fmaxf(red[tid], red[tid + s]);
        __syncthreads();
    }
    const float M = red[0];
    __syncthreads();
    red[tid] = ps0 * __expf(pm0 - M) + ps1 * __expf(pm1 - M) + ps2 * __expf(pm2 - M);
    __syncthreads();
#pragma unroll
    for (int s = 128; s > 0; s >>= 1) {
        if (tid < s) red[tid] += red[tid + s];
        __syncthreads();
    }
    const float inv = 1.0f / red[0];

    if (tid < nrows)
        out[r0 + tid] = __expf(s_sc[tid] - M) * inv;

    // ---------------- reset counters for next graph replay ------------------
    __threadfence();
    __syncthreads();
    if (tid == 0) {
        unsigned d = atomicAdd(&g_done, 1u) + 1;
        if (d == GRID) {
            g_bar = 0;
            g_done = 0;
            __threadfence();
        }
    }
}

// ---------------------------------------------------------------------------
extern "C" void kernel_launch(void* const* d_in, const int* in_sizes, int n_in,
                              void* d_out, int out_size) {
    const float* hidden = (const float*)d_in[0];   // [H]
    const float* enc    = (const float*)d_in[1];   // [S, H]
    const float* W      = (const float*)d_in[2];   // [H, H]
    float* out          = (float*)d_out;           // [S]

    cudaFuncSetAttribute(fused_kernel,
                         cudaFuncAttributeMaxDynamicSharedMemorySize, SMEM_DYN);
    fused_kernel<<<GRID, BLK, SMEM_DYN>>>(W, hidden, enc, out);
}

// round 17
// speedup vs baseline: 1.3186x; 1.0340x over previous
#include <cuda_runtime.h>
#include <math_constants.h>

#define H 1024
#define S 32768
#define GRID 256
#define BLK 256
#define ROWS_PER_BLK (S / GRID)          // 128
#define TILE_ROWS 8
#define NTILES (ROWS_PER_BLK / TILE_ROWS) // 16
#define STAGES 3
#define TILE_BYTES (TILE_ROWS * H * 4)    // 32768
#define TILE_F4 (TILE_ROWS * H / 4)       // 2048
#define SMEM_DYN (STAGES * TILE_BYTES)    // 98304
#define NSLICES 256                       // P0: 4 d-rows per slice (all blocks)

// Scratch (no allocations allowed)
__device__ float g_vpart[NSLICES * H];    // 1 MB
__device__ float g_v[H];
__device__ float g_bmax[GRID];
__device__ float g_bsum[GRID];
__device__ unsigned g_cnt0;      // P0-done count   (zero-init; self-resetting)
__device__ unsigned g_cnt1;      // P1-done count
__device__ volatile unsigned g_vflag;     // v ready
__device__ unsigned g_bar;       // epilogue barrier
__device__ unsigned g_done;      // reset counter

__device__ __forceinline__ void mbar_wait(unsigned mbar, unsigned parity) {
    asm volatile(
        "{\n\t"
        ".reg .pred P;\n\t"
        "W_%=:\n\t"
        "mbarrier.try_wait.parity.acquire.cta.shared::cta.b64 P, [%0], %1, 0x989680;\n\t"
        "@P bra D_%=;\n\t"
        "bra W_%=;\n\t"
        "D_%=:\n\t"
        "}" :: "r"(mbar), "r"(parity) : "memory");
}

__device__ __forceinline__ void bulk_fetch(unsigned ba, float4* dst, const char* src) {
    asm volatile("mbarrier.arrive.expect_tx.shared.b64 _, [%0], %1;"
                 :: "r"(ba), "r"(TILE_BYTES) : "memory");
    unsigned da = (unsigned)__cvta_generic_to_shared(dst);
    asm volatile("cp.async.bulk.shared::cta.global.mbarrier::complete_tx::bytes "
                 "[%0], [%1], %2, [%3];"
                 :: "r"(da), "l"(src), "r"(TILE_BYTES), "r"(ba) : "memory");
}

__global__ __launch_bounds__(BLK, 2) void fused_kernel(
    const float* __restrict__ W,
    const float* __restrict__ hidden,
    const float* __restrict__ enc,
    float* __restrict__ out)
{
    extern __shared__ float4 tile[];                   // [STAGES][TILE_F4]
    __shared__ __align__(8) unsigned long long mbar[STAGES];
    __shared__ float s_sc[ROWS_PER_BLK];
    __shared__ float red[BLK];

    const int tid  = threadIdx.x;
    const int warp = tid >> 5;
    const int lane = tid & 31;
    const int b    = blockIdx.x;

    const char* src_base = reinterpret_cast<const char*>(enc)
                         + (size_t)b * ROWS_PER_BLK * H * 4;

    // ---- t=0: mbarrier init + launch ALL prefetches before anything else --
    if (tid == 0) {
#pragma unroll
        for (int s = 0; s < STAGES; s++) {
            unsigned a = (unsigned)__cvta_generic_to_shared(&mbar[s]);
            asm volatile("mbarrier.init.shared.b64 [%0], 1;" :: "r"(a) : "memory");
        }
        asm volatile("fence.proxy.async.shared::cta;" ::: "memory");
#pragma unroll
        for (int s = 0; s < STAGES; s++) {
            unsigned ba = (unsigned)__cvta_generic_to_shared(&mbar[s]);
            bulk_fetch(ba, tile + s * TILE_F4, src_base + (size_t)s * TILE_BYTES);
        }
    }

    // ---- P0: v partials — ALL 256 blocks, 4 d-rows each (16 indep loads) --
    {
        const int d0 = b * 4;
        float acc0 = 0.f, acc1 = 0.f, acc2 = 0.f, acc3 = 0.f;
#pragma unroll
        for (int dd = 0; dd < 4; dd++) {
            const float hd = hidden[d0 + dd];
            const float* wr = W + (size_t)(d0 + dd) * H;
            acc0 += wr[tid      ] * hd;
            acc1 += wr[tid + 256] * hd;
            acc2 += wr[tid + 512] * hd;
            acc3 += wr[tid + 768] * hd;
        }
        g_vpart[b * H + tid      ] = acc0;
        g_vpart[b * H + tid + 256] = acc1;
        g_vpart[b * H + tid + 512] = acc2;
        g_vpart[b * H + tid + 768] = acc3;
    }
    __threadfence();
    __syncthreads();
    if (tid == 0) atomicAdd(&g_cnt0, 1u);

    // ---- P1: blocks 0..127 reduce partials -> g_v (warp per h) ------------
    if (b < 128) {
        if (tid == 0) {
            while (*(volatile unsigned*)&g_cnt0 < GRID) __nanosleep(32);
        }
        __syncthreads();
        __threadfence();
        const int h = b * 8 + warp;
        float a0 = g_vpart[(lane      ) * H + h];
        float a1 = g_vpart[(lane +  32) * H + h];
        float a2 = g_vpart[(lane +  64) * H + h];
        float a3 = g_vpart[(lane +  96) * H + h];
        float a4 = g_vpart[(lane + 128) * H + h];
        float a5 = g_vpart[(lane + 160) * H + h];
        float a6 = g_vpart[(lane + 192) * H + h];
        float a7 = g_vpart[(lane + 224) * H + h];
        float a = ((a0 + a1) + (a2 + a3)) + ((a4 + a5) + (a6 + a7));
#pragma unroll
        for (int o = 16; o > 0; o >>= 1) a += __shfl_xor_sync(0xFFFFFFFFu, a, o);
        if (lane == 0) g_v[h] = a;
        __threadfence();
        __syncthreads();
        if (tid == 0) {
            unsigned prev = atomicAdd(&g_cnt1, 1u);
            if (prev == 127u) { __threadfence(); g_vflag = 1u; }
        }
    }

    // ---- wait until v is ready (TMA tiles keep landing meanwhile) ---------
    if (tid == 0) {
        while (g_vflag == 0u) __nanosleep(32);
    }
    __syncthreads();
    __threadfence();

    // v resident in registers (same lane pattern for every row)
    float4 vr[8];
    const float4* v4 = reinterpret_cast<const float4*>(g_v);
#pragma unroll
    for (int k = 0; k < 8; k++) vr[k] = v4[lane + k * 32];

    // ---- P2: consume the pipeline (exact R6 geometry) ---------------------
#pragma unroll 1
    for (int t = 0; t < NTILES; t++) {
        const int st = t % STAGES;
        unsigned ba = (unsigned)__cvta_generic_to_shared(&mbar[st]);
        mbar_wait(ba, (t / STAGES) & 1);

        const float4* rowp = tile + st * TILE_F4 + warp * (H / 4);
        float acc = 0.f;
#pragma unroll
        for (int k = 0; k < 8; k++) {
            float4 e = rowp[lane + k * 32];
            acc += e.x * vr[k].x + e.y * vr[k].y + e.z * vr[k].z + e.w * vr[k].w;
        }
#pragma unroll
        for (int o = 16; o > 0; o >>= 1) acc += __shfl_xor_sync(0xFFFFFFFFu, acc, o);
        if (lane == 0) s_sc[t * TILE_ROWS + warp] = acc;

        __syncthreads();   // all warps done reading stage st
        if (tid == 0 && t + STAGES < NTILES) {
            bulk_fetch(ba, tile + st * TILE_F4,
                       src_base + (size_t)(t + STAGES) * TILE_BYTES);
        }
    }

    // ---- block (max, expsum) over its 128 scores --------------------------
    red[tid] = (tid < ROWS_PER_BLK) ? s_sc[tid] : -CUDART_INF_F;
    __syncthreads();
#pragma unroll
    for (int s = 128; s > 0; s >>= 1) {
        if (tid < s) red[tid] = fmaxf(red[tid], red[tid + s]);
        __syncthreads();
    }
    const float Mb = red[0];
    __syncthreads();
    red[tid] = (tid < ROWS_PER_BLK) ? __expf(s_sc[tid] - Mb) : 0.f;
    __syncthreads();
#pragma unroll
    for (int s = 128; s > 0; s >>= 1) {
        if (tid < s) red[tid] += red[tid + s];
        __syncthreads();
    }
    if (tid == 0) {
        g_bmax[b] = Mb;
        g_bsum[b] = red[0];
    }

    // ---- epilogue grid barrier -------------------------------------------
    __threadfence();
    __syncthreads();
    if (tid == 0) {
        atomicAdd(&g_bar, 1u);
        while (*(volatile unsigned*)&g_bar < GRID) __nanosleep(32);
    }
    __syncthreads();
    __threadfence();

    // ---- P3: redundant pair-reduce (256 pairs == BLK) + normalize ---------
    const float pm = g_bmax[tid];
    const float ps = g_bsum[tid];
    red[tid] = pm;
    __syncthreads();
#pragma unroll
    for (int s = 128; s > 0; s >>= 1) {
        if (tid < s) red[tid] = fmaxf(red[tid], red[tid + s]);
        __syncthreads();
    }
    const float M = red[0];
    __syncthreads();
    red[tid] = ps * __expf(pm - M);
    __syncthreads();
#pragma unroll
    for (int s = 128; s > 0; s >>= 1) {
        if (tid < s) red[tid] += red[tid + s];
        __syncthreads();
    }
    const float inv = 1.0f / red[0];

    if (tid < ROWS_PER_BLK)
        out[b * ROWS_PER_BLK + tid] = __expf(s_sc[tid] - M) * inv;

    // ---- reset counters for next graph replay -----------------------------
    __threadfence();
    __syncthreads();
    if (tid == 0) {
        unsigned d = atomicAdd(&g_done, 1u) + 1;
        if (d == GRID) {
            g_cnt0 = 0;
            g_cnt1 = 0;
            g_vflag = 0;
            g_bar = 0;
            g_done = 0;
            __threadfence();
        }
    }
}

// ---------------------------------------------------------------------------
extern "C" void kernel_launch(void* const* d_in, const int* in_sizes, int n_in,
                              void* d_out, int out_size) {
    const float* hidden = (const float*)d_in[0];   // [H]
    const float* enc    = (const float*)d_in[1];   // [S, H]
    const float* W      = (const float*)d_in[2];   // [H, H]
    float* out          = (float*)d_out;           // [S]

    cudaFuncSetAttribute(fused_kernel,
                         cudaFuncAttributeMaxDynamicSharedMemorySize, SMEM_DYN);
    fused_kernel<<<GRID, BLK, SMEM_DYN>>>(W, hidden, enc, out);
}